// round 1
// baseline (speedup 1.0000x reference)
#include <cuda_runtime.h>
#include <math.h>

#define Bz 2
#define Lz 1024
#define Dz 1024
#define DIz 2048
#define E2 4096
#define RK 64
#define NS 16
#define XD 96
#define BL (Bz*Lz)

// ---------------- scratch (static device globals; no allocation) ----------------
__device__ float g_xz0[BL*E2];   // xz for dir f  (original coords)
__device__ float g_xz1[BL*E2];   // xz for dir r  (original coords)
__device__ float g_xc0[BL*DIz];  // conv+silu output, processing coords
__device__ float g_xc1[BL*DIz];
__device__ float g_xd0[BL*XD];   // x_dbl, processing coords
__device__ float g_xd1[BL*XD];
__device__ float g_dt0[BL*DIz];  // softplus(dt), processing coords
__device__ float g_dt1[BL*DIz];
__device__ float g_y[BL*E2];     // [y_f | y_r-unreversed], original coords
__device__ float g_A0[DIz*NS];   // A = -exp(Alog)
__device__ float g_A1[DIz*NS];

// ---------------- A precompute ----------------
__global__ void prep_A(const float* __restrict__ Af, const float* __restrict__ Ar) {
    int i = blockIdx.x * blockDim.x + threadIdx.x;
    if (i < DIz*NS) {
        g_A0[i] = -expf(Af[i]);
        g_A1[i] = -expf(Ar[i]);
    }
}

// ---------------- generic SGEMM: C[M,N] (op) A[M,K](lda) * B[N,K](ldb)^T ----------------
// EPI: 0 = write, 1 = softplus(acc + bias[col]), 2 = accumulate into C
template<int EPI>
__global__ void __launch_bounds__(256) sgemm_nt(
    const float* __restrict__ A, int lda,
    const float* __restrict__ Bm, int ldb,
    float* __restrict__ C, int ldc,
    int M, int N, int K,
    const float* __restrict__ bias)
{
    __shared__ __align__(16) float As[16][68];
    __shared__ __align__(16) float Bs[16][68];

    int tid = threadIdx.x;
    int m0 = blockIdx.y * 64;
    int n0 = blockIdx.x * 64;
    int ar = tid >> 2;          // 0..63 row within tile
    int ac = (tid & 3) * 4;     // k offset {0,4,8,12}
    int ty = tid >> 4;          // 0..15
    int tx = tid & 15;          // 0..15

    float acc[4][4] = {};

    const float* Ag = A + (long)(m0 + ar) * lda + ac;
    const float* Bg = Bm + (long)(n0 + ar) * ldb + ac;
    bool bvalid = (n0 + ar) < N;

    for (int kt = 0; kt < K; kt += 16) {
        float4 av = *(const float4*)(Ag + kt);
        float4 bv = bvalid ? *(const float4*)(Bg + kt) : make_float4(0.f, 0.f, 0.f, 0.f);
        As[ac + 0][ar] = av.x; As[ac + 1][ar] = av.y;
        As[ac + 2][ar] = av.z; As[ac + 3][ar] = av.w;
        Bs[ac + 0][ar] = bv.x; Bs[ac + 1][ar] = bv.y;
        Bs[ac + 2][ar] = bv.z; Bs[ac + 3][ar] = bv.w;
        __syncthreads();
#pragma unroll
        for (int k = 0; k < 16; k++) {
            float4 a4 = *(const float4*)&As[k][ty * 4];
            float4 b4 = *(const float4*)&Bs[k][tx * 4];
            float aa[4] = {a4.x, a4.y, a4.z, a4.w};
            float bb[4] = {b4.x, b4.y, b4.z, b4.w};
#pragma unroll
            for (int i = 0; i < 4; i++)
#pragma unroll
                for (int j = 0; j < 4; j++)
                    acc[i][j] = fmaf(aa[i], bb[j], acc[i][j]);
        }
        __syncthreads();
    }

#pragma unroll
    for (int i = 0; i < 4; i++) {
        int row = m0 + ty * 4 + i;
#pragma unroll
        for (int j = 0; j < 4; j++) {
            int col = n0 + tx * 4 + j;
            if (row < M && col < N) {
                float v = acc[i][j];
                if (EPI == 1) {
                    v += bias[col];
                    v = (v > 20.f) ? v : log1pf(__expf(v));
                }
                if (EPI == 2) v += C[(long)row * ldc + col];
                C[(long)row * ldc + col] = v;
            }
        }
    }
}

// ---------------- causal depthwise conv (K=4) + SiLU, handles reversal ----------------
__global__ void conv_silu(const float* __restrict__ Wf, const float* __restrict__ bf,
                          const float* __restrict__ Wr, const float* __restrict__ br)
{
    int idx = blockIdx.x * blockDim.x + threadIdx.x;   // total 2*BL*DIz
    int d = idx & (DIz - 1);
    int t = idx >> 11;
    int m = t & (Lz - 1);      // processing coordinate
    t >>= 10;
    int b = t & 1;
    int dir = t >> 1;

    const float* xz = dir ? g_xz1 : g_xz0;
    const float* W  = dir ? Wr : Wf;
    const float* bc = dir ? br : bf;

    float acc = bc[d];
#pragma unroll
    for (int k = 0; k < 4; k++) {
        int mp = m - 3 + k;
        if (mp >= 0) {
            int orig = dir ? (Lz - 1 - mp) : mp;
            acc = fmaf(W[d * 4 + k], xz[((b << 10) + orig) * E2 + d], acc);
        }
    }
    float s = acc / (1.f + __expf(-acc));   // silu
    (dir ? g_xc1 : g_xc0)[((b << 10) + m) * DIz + d] = s;
}

// ---------------- selective scan (both dirs), fused Dskip + silu(z) gate + un-reverse ----------------
// one thread per (dir,b,d,n); 16 lanes per channel; 2 channels per warp
__global__ void __launch_bounds__(256) scan_kernel(const float* __restrict__ Dskf,
                                                   const float* __restrict__ Dskr)
{
    int gw = (blockIdx.x * blockDim.x + threadIdx.x) >> 5;
    int lane = threadIdx.x & 31;
    int dir = gw >> 11;
    int rem = gw & 2047;
    int c = (rem << 1) | (lane >> 4);   // channel = b*2048 + d
    int b = c >> 11;
    int d = c & 2047;
    int n = lane & 15;

    const float* dt = dir ? g_dt1 : g_dt0;
    const float* xc = dir ? g_xc1 : g_xc0;
    const float* xd = dir ? g_xd1 : g_xd0;
    const float* xz = dir ? g_xz1 : g_xz0;
    const float* Aa = dir ? g_A1  : g_A0;

    float An = Aa[d * NS + n];
    float Dd = (dir ? Dskr : Dskf)[d];

    int base = b * Lz;
    const float* dtp = dt + (long)base * DIz + d;
    const float* up  = xc + (long)base * DIz + d;
    const float* bcp = xd + (long)base * XD + 64 + n;

    int orig0 = dir ? (Lz - 1) : 0;
    int dz = dir ? -E2 : E2;
    int zoff = (base + orig0) * E2 + DIz + d;          // z = xz[..., DI + d] at original coords
    int yoff = (base + orig0) * E2 + dir * DIz + d;    // ycat column block

    float h = 0.f;
    for (int m = 0; m < Lz; m++) {
        float delta = *dtp;
        float u = *up;
        float Bv = bcp[0];
        float Cv = bcp[16];
        float a = __expf(delta * An);
        h = fmaf(a, h, delta * u * Bv);
        float s = Cv * h;
        s += __shfl_xor_sync(0xffffffffu, s, 1, 16);
        s += __shfl_xor_sync(0xffffffffu, s, 2, 16);
        s += __shfl_xor_sync(0xffffffffu, s, 4, 16);
        s += __shfl_xor_sync(0xffffffffu, s, 8, 16);
        if (n == 0) {
            float y = fmaf(u, Dd, s);
            float z = xz[zoff];
            y *= z / (1.f + __expf(-z));   // * silu(z)
            g_y[yoff] = y;
        }
        dtp += DIz; up += DIz; bcp += XD; zoff += dz; yoff += dz;
    }
}

// ---------------- launch ----------------
extern "C" void kernel_launch(void* const* d_in, const int* in_sizes, int n_in,
                              void* d_out, int out_size)
{
    (void)in_sizes; (void)n_in; (void)out_size;
    const float* x       = (const float*)d_in[0];
    const float* Win_f   = (const float*)d_in[1];
    const float* Wconv_f = (const float*)d_in[2];
    const float* bconv_f = (const float*)d_in[3];
    const float* Wx_f    = (const float*)d_in[4];
    const float* Wdt_f   = (const float*)d_in[5];
    const float* bdt_f   = (const float*)d_in[6];
    const float* Alog_f  = (const float*)d_in[7];
    const float* Dsk_f   = (const float*)d_in[8];
    const float* Wout_f  = (const float*)d_in[9];
    const float* Win_r   = (const float*)d_in[10];
    const float* Wconv_r = (const float*)d_in[11];
    const float* bconv_r = (const float*)d_in[12];
    const float* Wx_r    = (const float*)d_in[13];
    const float* Wdt_r   = (const float*)d_in[14];
    const float* bdt_r   = (const float*)d_in[15];
    const float* Alog_r  = (const float*)d_in[16];
    const float* Dsk_r   = (const float*)d_in[17];
    const float* Wout_r  = (const float*)d_in[18];
    float* out = (float*)d_out;

    float *xz0, *xz1, *xc0, *xc1, *xd0, *xd1, *dt0, *dt1, *yb;
    cudaGetSymbolAddress((void**)&xz0, g_xz0);
    cudaGetSymbolAddress((void**)&xz1, g_xz1);
    cudaGetSymbolAddress((void**)&xc0, g_xc0);
    cudaGetSymbolAddress((void**)&xc1, g_xc1);
    cudaGetSymbolAddress((void**)&xd0, g_xd0);
    cudaGetSymbolAddress((void**)&xd1, g_xd1);
    cudaGetSymbolAddress((void**)&dt0, g_dt0);
    cudaGetSymbolAddress((void**)&dt1, g_dt1);
    cudaGetSymbolAddress((void**)&yb,  g_y);

    prep_A<<<(DIz*NS + 255) / 256, 256>>>(Alog_f, Alog_r);

    // GEMM1: xz = x * Win^T  (position-independent -> no reversal needed here)
    dim3 g1(E2 / 64, BL / 64);
    sgemm_nt<0><<<g1, 256>>>(x, Dz, Win_f, Dz, xz0, E2, BL, E2, Dz, nullptr);
    sgemm_nt<0><<<g1, 256>>>(x, Dz, Win_r, Dz, xz1, E2, BL, E2, Dz, nullptr);

    // depthwise causal conv + silu (reads reversed for dir r, writes processing coords)
    conv_silu<<<(2 * BL * DIz) / 256, 256>>>(Wconv_f, bconv_f, Wconv_r, bconv_r);

    // x_dbl = xc * Wx^T
    dim3 g2((XD + 63) / 64, BL / 64);
    sgemm_nt<0><<<g2, 256>>>(xc0, DIz, Wx_f, DIz, xd0, XD, BL, XD, DIz, nullptr);
    sgemm_nt<0><<<g2, 256>>>(xc1, DIz, Wx_r, DIz, xd1, XD, BL, XD, DIz, nullptr);

    // dt = softplus(x_dbl[:, :64] * Wdt^T + bdt)
    dim3 g3(DIz / 64, BL / 64);
    sgemm_nt<1><<<g3, 256>>>(xd0, XD, Wdt_f, RK, dt0, DIz, BL, DIz, RK, bdt_f);
    sgemm_nt<1><<<g3, 256>>>(xd1, XD, Wdt_r, RK, dt1, DIz, BL, DIz, RK, bdt_r);

    // selective scan (both dirs), fused gate + un-reverse into g_y
    scan_kernel<<<512, 256>>>(Dsk_f, Dsk_r);

    // out = y_f * Wout_f^T + y_r * Wout_r^T
    dim3 g4(Dz / 64, BL / 64);
    sgemm_nt<0><<<g4, 256>>>(yb,        E2, Wout_f, DIz, out, Dz, BL, Dz, DIz, nullptr);
    sgemm_nt<2><<<g4, 256>>>(yb + DIz,  E2, Wout_r, DIz, out, Dz, BL, Dz, DIz, nullptr);
}

// round 5
// speedup vs baseline: 1.2889x; 1.2889x over previous
#include <cuda_runtime.h>
#include <cuda_bf16.h>
#include <math.h>
#include <stdint.h>

#define Bz 2
#define Lz 1024
#define Dz 1024
#define DIz 2048
#define E2 4096
#define RK 64
#define NS 16
#define XD 96
#define BL (Bz*Lz)

// ---------------- scratch (static device globals; no allocation) ----------------
__device__ float g_xz0[BL*E2];
__device__ float g_xz1[BL*E2];
__device__ float g_xc0[BL*DIz];
__device__ float g_xc1[BL*DIz];
__device__ float g_xd0[BL*XD];
__device__ float g_xd1[BL*XD];
__device__ float g_dt0[BL*DIz];
__device__ float g_dt1[BL*DIz];
__device__ float g_y[BL*E2];
__device__ float g_A0[DIz*NS];
__device__ float g_A1[DIz*NS];
__device__ float g_wcat[Dz*E2];   // [Wout_f | Wout_r] K-concat

__device__ __forceinline__ uint32_t smem_u32(const void* p) {
    uint32_t a;
    asm("{ .reg .u64 t; cvta.to.shared.u64 t, %1; cvt.u32.u64 %0, t; }" : "=r"(a) : "l"(p));
    return a;
}

#define LDSM_X4(r0, r1, r2, r3, addr) \
    asm volatile("ldmatrix.sync.aligned.m8n8.x4.shared.b16 {%0,%1,%2,%3}, [%4];" \
        : "=r"(r0), "=r"(r1), "=r"(r2), "=r"(r3) : "r"(addr))

#define MMA_BF16(d, a, b0, b1) \
    asm volatile("mma.sync.aligned.m16n8k16.row.col.f32.bf16.bf16.f32 " \
        "{%0,%1,%2,%3}, {%4,%5,%6,%7}, {%8,%9}, {%0,%1,%2,%3};" \
        : "+f"((d)[0]), "+f"((d)[1]), "+f"((d)[2]), "+f"((d)[3]) \
        : "r"((a)[0]), "r"((a)[1]), "r"((a)[2]), "r"((a)[3]), "r"(b0), "r"(b1))

// ---------------- bf16x3 GEMM via mma.sync:  C[M,N] = A[M,K](lda) * B[N,K](ldb)^T ----------------
// tile 128x128, BK=64, 8 warps (4m x 2n), warp tile 32x64.
// 3 accumulate passes: Ahi*Bhi + Alo*Bhi + Ahi*Blo.
#define BKt 64
#define LDT 72                    // padded bf16 row stride
#define BUF (128*LDT)             // elements per buffer
#define SM_BYTES (4*BUF*2)        // 73728

template<int EPI>   // 0 = write, 1 = softplus(acc + bias[col])
__global__ void __launch_bounds__(256) mma_gemm(
    const float* __restrict__ A, int lda,
    const float* __restrict__ B, int ldb,
    float* __restrict__ C, int ldc,
    int M, int N, int K,
    const float* __restrict__ bias)
{
    extern __shared__ __align__(16) char smraw[];
    __nv_bfloat16* sm = (__nv_bfloat16*)smraw;
    const uint32_t sbase = smem_u32(sm);

    const int tid = threadIdx.x;
    const int wid = tid >> 5;
    const int lane = tid & 31;
    const int m0 = blockIdx.y * 128;
    const int n0 = blockIdx.x * 128;

    const int row = tid >> 1;          // 0..127
    const int seg = tid & 1;           // 32-float half of the 64-wide k-chunk
    const float* Ag = A + (size_t)(m0 + row) * lda + seg * 32;
    const float* Bg = B + (size_t)(n0 + row) * ldb + seg * 32;
    const bool bok = (n0 + row) < N;

    const int wm = (wid >> 1) * 32;
    const int wn = (wid & 1) * 64;

    // ldmatrix lane->address mapping
    const int a_r = lane & 15;
    const int a_c = (lane >> 4) * 8;
    const int b_r = (lane & 7) + ((lane >> 4) << 3);
    const int b_c = ((lane >> 3) & 1) * 8;

    float acc[2][8][4];
#pragma unroll
    for (int i = 0; i < 2; i++)
#pragma unroll
        for (int j = 0; j < 8; j++)
#pragma unroll
            for (int k = 0; k < 4; k++) acc[i][j][k] = 0.f;

    for (int kt = 0; kt < K; kt += BKt) {
        if (kt) __syncthreads();

        // ---- load fp32, split to bf16 hi/lo, store to smem ----
#pragma unroll
        for (int i = 0; i < 8; i++) {
            float4 av = *(const float4*)(Ag + kt + i * 4);
            float4 bv = bok ? *(const float4*)(Bg + kt + i * 4)
                            : make_float4(0.f, 0.f, 0.f, 0.f);
            int off = row * LDT + seg * 32 + i * 4;
            {
                __nv_bfloat162 h01 = __floats2bfloat162_rn(av.x, av.y);
                __nv_bfloat162 h23 = __floats2bfloat162_rn(av.z, av.w);
                float2 f01 = __bfloat1622float2(h01);
                float2 f23 = __bfloat1622float2(h23);
                __nv_bfloat162 l01 = __floats2bfloat162_rn(av.x - f01.x, av.y - f01.y);
                __nv_bfloat162 l23 = __floats2bfloat162_rn(av.z - f23.x, av.w - f23.y);
                *(uint2*)(sm + off)       = make_uint2(*(uint32_t*)&h01, *(uint32_t*)&h23);
                *(uint2*)(sm + BUF + off) = make_uint2(*(uint32_t*)&l01, *(uint32_t*)&l23);
            }
            {
                __nv_bfloat162 h01 = __floats2bfloat162_rn(bv.x, bv.y);
                __nv_bfloat162 h23 = __floats2bfloat162_rn(bv.z, bv.w);
                float2 f01 = __bfloat1622float2(h01);
                float2 f23 = __bfloat1622float2(h23);
                __nv_bfloat162 l01 = __floats2bfloat162_rn(bv.x - f01.x, bv.y - f01.y);
                __nv_bfloat162 l23 = __floats2bfloat162_rn(bv.z - f23.x, bv.w - f23.y);
                *(uint2*)(sm + 2*BUF + off) = make_uint2(*(uint32_t*)&h01, *(uint32_t*)&h23);
                *(uint2*)(sm + 3*BUF + off) = make_uint2(*(uint32_t*)&l01, *(uint32_t*)&l23);
            }
        }
        __syncthreads();

        // ---- 3 mma passes ----
#pragma unroll 1
        for (int pass = 0; pass < 3; pass++) {
            const int aoff = (pass == 1) ? BUF : 0;
            const int boff = (pass == 2) ? 3 * BUF : 2 * BUF;
#pragma unroll
            for (int ks = 0; ks < 4; ks++) {
                uint32_t ar[2][4];
#pragma unroll
                for (int mi = 0; mi < 2; mi++) {
                    uint32_t ad = sbase + 2u * (aoff + (wm + mi * 16 + a_r) * LDT + ks * 16 + a_c);
                    LDSM_X4(ar[mi][0], ar[mi][1], ar[mi][2], ar[mi][3], ad);
                }
                uint32_t br[4][4];
#pragma unroll
                for (int bj = 0; bj < 4; bj++) {
                    uint32_t bd = sbase + 2u * (boff + (wn + bj * 16 + b_r) * LDT + ks * 16 + b_c);
                    LDSM_X4(br[bj][0], br[bj][1], br[bj][2], br[bj][3], bd);
                }
#pragma unroll
                for (int mi = 0; mi < 2; mi++)
#pragma unroll
                    for (int nj = 0; nj < 8; nj++)
                        MMA_BF16(acc[mi][nj], ar[mi], br[nj >> 1][(nj & 1) * 2], br[nj >> 1][(nj & 1) * 2 + 1]);
            }
        }
    }

    // ---- epilogue ----
    const int gr = lane >> 2;
    const int tc = (lane & 3) * 2;
#pragma unroll
    for (int mi = 0; mi < 2; mi++) {
#pragma unroll
        for (int nj = 0; nj < 8; nj++) {
            int r = m0 + wm + mi * 16 + gr;
            int c = n0 + wn + nj * 8 + tc;
            if (c < N) {
                float v0 = acc[mi][nj][0], v1 = acc[mi][nj][1];
                float v2 = acc[mi][nj][2], v3 = acc[mi][nj][3];
                if (EPI == 1) {
                    float b0 = bias[c], b1 = bias[c + 1];
                    v0 += b0; v1 += b1; v2 += b0; v3 += b1;
                    v0 = (v0 > 20.f) ? v0 : log1pf(__expf(v0));
                    v1 = (v1 > 20.f) ? v1 : log1pf(__expf(v1));
                    v2 = (v2 > 20.f) ? v2 : log1pf(__expf(v2));
                    v3 = (v3 > 20.f) ? v3 : log1pf(__expf(v3));
                }
                float* p0 = C + (size_t)r * ldc + c;
                float* p1 = C + (size_t)(r + 8) * ldc + c;
                p0[0] = v0; p0[1] = v1;
                p1[0] = v2; p1[1] = v3;
            }
        }
    }
}

// ---------------- A precompute + Wout packing ----------------
__global__ void prep_A(const float* __restrict__ Af, const float* __restrict__ Ar) {
    int i = blockIdx.x * blockDim.x + threadIdx.x;
    if (i < DIz * NS) {
        g_A0[i] = -expf(Af[i]);
        g_A1[i] = -expf(Ar[i]);
    }
}
__global__ void pack_wcat(const float* __restrict__ Wf, const float* __restrict__ Wr) {
    int i = blockIdx.x * blockDim.x + threadIdx.x;   // over Dz*E2
    int n = i >> 12;
    int k = i & 4095;
    g_wcat[i] = (k < DIz) ? Wf[n * DIz + k] : Wr[n * DIz + (k - DIz)];
}

// ---------------- causal depthwise conv (K=4) + SiLU ----------------
__global__ void conv_silu(const float* __restrict__ Wf, const float* __restrict__ bf,
                          const float* __restrict__ Wr, const float* __restrict__ br)
{
    int idx = blockIdx.x * blockDim.x + threadIdx.x;
    int d = idx & (DIz - 1);
    int t = idx >> 11;
    int m = t & (Lz - 1);
    t >>= 10;
    int b = t & 1;
    int dir = t >> 1;

    const float* xz = dir ? g_xz1 : g_xz0;
    const float* W  = dir ? Wr : Wf;
    const float* bc = dir ? br : bf;

    float acc = bc[d];
#pragma unroll
    for (int k = 0; k < 4; k++) {
        int mp = m - 3 + k;
        if (mp >= 0) {
            int orig = dir ? (Lz - 1 - mp) : mp;
            acc = fmaf(W[d * 4 + k], xz[((b << 10) + orig) * E2 + d], acc);
        }
    }
    float s = acc / (1.f + __expf(-acc));
    (dir ? g_xc1 : g_xc0)[((b << 10) + m) * DIz + d] = s;
}

// ---------------- selective scan ----------------
__global__ void __launch_bounds__(256) scan_kernel(const float* __restrict__ Dskf,
                                                   const float* __restrict__ Dskr)
{
    int gw = (blockIdx.x * blockDim.x + threadIdx.x) >> 5;
    int lane = threadIdx.x & 31;
    int dir = gw >> 11;
    int rem = gw & 2047;
    int c = (rem << 1) | (lane >> 4);
    int b = c >> 11;
    int d = c & 2047;
    int n = lane & 15;

    const float* dt = dir ? g_dt1 : g_dt0;
    const float* xc = dir ? g_xc1 : g_xc0;
    const float* xd = dir ? g_xd1 : g_xd0;
    const float* xz = dir ? g_xz1 : g_xz0;
    const float* Aa = dir ? g_A1  : g_A0;

    float An = Aa[d * NS + n];
    float Dd = (dir ? Dskr : Dskf)[d];

    int base = b * Lz;
    const float* dtp = dt + (size_t)base * DIz + d;
    const float* up  = xc + (size_t)base * DIz + d;
    const float* bcp = xd + (size_t)base * XD + 64 + n;

    int orig0 = dir ? (Lz - 1) : 0;
    int dz = dir ? -E2 : E2;
    int zoff = (base + orig0) * E2 + DIz + d;
    int yoff = (base + orig0) * E2 + dir * DIz + d;

    float h = 0.f;
    for (int m = 0; m < Lz; m++) {
        float delta = *dtp;
        float u = *up;
        float Bv = bcp[0];
        float Cv = bcp[16];
        float a = __expf(delta * An);
        h = fmaf(a, h, delta * u * Bv);
        float s = Cv * h;
        s += __shfl_xor_sync(0xffffffffu, s, 1, 16);
        s += __shfl_xor_sync(0xffffffffu, s, 2, 16);
        s += __shfl_xor_sync(0xffffffffu, s, 4, 16);
        s += __shfl_xor_sync(0xffffffffu, s, 8, 16);
        if (n == 0) {
            float y = fmaf(u, Dd, s);
            float z = xz[zoff];
            y *= z / (1.f + __expf(-z));
            g_y[yoff] = y;
        }
        dtp += DIz; up += DIz; bcp += XD; zoff += dz; yoff += dz;
    }
}

// ---------------- launch ----------------
extern "C" void kernel_launch(void* const* d_in, const int* in_sizes, int n_in,
                              void* d_out, int out_size)
{
    (void)in_sizes; (void)n_in; (void)out_size;
    const float* x       = (const float*)d_in[0];
    const float* Win_f   = (const float*)d_in[1];
    const float* Wconv_f = (const float*)d_in[2];
    const float* bconv_f = (const float*)d_in[3];
    const float* Wx_f    = (const float*)d_in[4];
    const float* Wdt_f   = (const float*)d_in[5];
    const float* bdt_f   = (const float*)d_in[6];
    const float* Alog_f  = (const float*)d_in[7];
    const float* Dsk_f   = (const float*)d_in[8];
    const float* Wout_f  = (const float*)d_in[9];
    const float* Win_r   = (const float*)d_in[10];
    const float* Wconv_r = (const float*)d_in[11];
    const float* bconv_r = (const float*)d_in[12];
    const float* Wx_r    = (const float*)d_in[13];
    const float* Wdt_r   = (const float*)d_in[14];
    const float* bdt_r   = (const float*)d_in[15];
    const float* Alog_r  = (const float*)d_in[16];
    const float* Dsk_r   = (const float*)d_in[17];
    const float* Wout_r  = (const float*)d_in[18];
    float* out = (float*)d_out;

    float *xz0, *xz1, *xc0, *xc1, *xd0, *xd1, *dt0, *dt1, *yb, *wc;
    cudaGetSymbolAddress((void**)&xz0, g_xz0);
    cudaGetSymbolAddress((void**)&xz1, g_xz1);
    cudaGetSymbolAddress((void**)&xc0, g_xc0);
    cudaGetSymbolAddress((void**)&xc1, g_xc1);
    cudaGetSymbolAddress((void**)&xd0, g_xd0);
    cudaGetSymbolAddress((void**)&xd1, g_xd1);
    cudaGetSymbolAddress((void**)&dt0, g_dt0);
    cudaGetSymbolAddress((void**)&dt1, g_dt1);
    cudaGetSymbolAddress((void**)&yb,  g_y);
    cudaGetSymbolAddress((void**)&wc,  g_wcat);

    cudaFuncSetAttribute(mma_gemm<0>, cudaFuncAttributeMaxDynamicSharedMemorySize, SM_BYTES);
    cudaFuncSetAttribute(mma_gemm<1>, cudaFuncAttributeMaxDynamicSharedMemorySize, SM_BYTES);

    prep_A<<<(DIz*NS + 255) / 256, 256>>>(Alog_f, Alog_r);
    pack_wcat<<<(Dz * E2) / 256, 256>>>(Wout_f, Wout_r);

    // GEMM1: xz = x * Win^T   M=2048 N=4096 K=1024
    mma_gemm<0><<<dim3(E2/128, BL/128), 256, SM_BYTES>>>(x, Dz, Win_f, Dz, xz0, E2, BL, E2, Dz, nullptr);
    mma_gemm<0><<<dim3(E2/128, BL/128), 256, SM_BYTES>>>(x, Dz, Win_r, Dz, xz1, E2, BL, E2, Dz, nullptr);

    conv_silu<<<(2 * BL * DIz) / 256, 256>>>(Wconv_f, bconv_f, Wconv_r, bconv_r);

    // GEMM2: x_dbl = xc * Wx^T  M=2048 N=96 K=2048
    mma_gemm<0><<<dim3(1, BL/128), 256, SM_BYTES>>>(xc0, DIz, Wx_f, DIz, xd0, XD, BL, XD, DIz, nullptr);
    mma_gemm<0><<<dim3(1, BL/128), 256, SM_BYTES>>>(xc1, DIz, Wx_r, DIz, xd1, XD, BL, XD, DIz, nullptr);

    // GEMM3: dt = softplus(x_dbl[:, :64] * Wdt^T + bdt)  M=2048 N=2048 K=64
    mma_gemm<1><<<dim3(DIz/128, BL/128), 256, SM_BYTES>>>(xd0, XD, Wdt_f, RK, dt0, DIz, BL, DIz, RK, bdt_f);
    mma_gemm<1><<<dim3(DIz/128, BL/128), 256, SM_BYTES>>>(xd1, XD, Wdt_r, RK, dt1, DIz, BL, DIz, RK, bdt_r);

    scan_kernel<<<512, 256>>>(Dsk_f, Dsk_r);

    // GEMM4: out = ycat * Wcat^T   M=2048 N=1024 K=4096
    mma_gemm<0><<<dim3(Dz/128, BL/128), 256, SM_BYTES>>>(yb, E2, wc, E2, out, Dz, BL, Dz, E2, nullptr);
}

// round 7
// speedup vs baseline: 1.6076x; 1.2473x over previous
#include <cuda_runtime.h>
#include <cuda_bf16.h>
#include <math.h>
#include <stdint.h>

#define Bz 2
#define Lz 1024
#define Dz 1024
#define DIz 2048
#define E2 4096
#define RK 64
#define NS 16
#define XD 96
#define BL (Bz*Lz)
#define KSPLIT 8

typedef __nv_bfloat16 bf16;

// ---------------- scratch ----------------
__device__ float g_xz0[BL*E2];
__device__ float g_xz1[BL*E2];
__device__ float g_xc0[BL*DIz];
__device__ float g_xc1[BL*DIz];
__device__ float g_xd0[BL*XD];
__device__ float g_xd1[BL*XD];
__device__ float g_xdp0[KSPLIT*BL*XD];
__device__ float g_xdp1[KSPLIT*BL*XD];
__device__ float g_dt0[BL*DIz];
__device__ float g_dt1[BL*DIz];
__device__ float g_A0[DIz*NS];
__device__ float g_A1[DIz*NS];

// bf16 hi/lo operand buffers
__device__ bf16 g_xh[BL*Dz],    g_xl[BL*Dz];
__device__ bf16 g_w1fh[E2*Dz],  g_w1fl[E2*Dz];
__device__ bf16 g_w1rh[E2*Dz],  g_w1rl[E2*Dz];
__device__ bf16 g_xch0[BL*DIz], g_xcl0[BL*DIz];
__device__ bf16 g_xch1[BL*DIz], g_xcl1[BL*DIz];
__device__ bf16 g_wxfh[XD*DIz], g_wxfl[XD*DIz];
__device__ bf16 g_wxrh[XD*DIz], g_wxrl[XD*DIz];
__device__ bf16 g_wdtfh[DIz*RK], g_wdtfl[DIz*RK];
__device__ bf16 g_wdtrh[DIz*RK], g_wdtrl[DIz*RK];
__device__ bf16 g_xdh0[BL*RK],  g_xdl0[BL*RK];
__device__ bf16 g_xdh1[BL*RK],  g_xdl1[BL*RK];
__device__ bf16 g_yh[BL*E2],    g_yl[BL*E2];
__device__ bf16 g_wch[Dz*E2],   g_wcl[Dz*E2];

__device__ __forceinline__ uint32_t smem_u32(const void* p) {
    uint32_t a;
    asm("{ .reg .u64 t; cvta.to.shared.u64 t, %1; cvt.u32.u64 %0, t; }" : "=r"(a) : "l"(p));
    return a;
}
__device__ __forceinline__ uint32_t swz(uint32_t o) { return o ^ (((o >> 7) & 7) << 4); }

#define CP_ASYNC(dst, src, sz) \
    asm volatile("cp.async.cg.shared.global [%0], [%1], 16, %2;" :: "r"(dst), "l"(src), "r"(sz))
#define CP_COMMIT() asm volatile("cp.async.commit_group;")
#define CP_WAIT1()  asm volatile("cp.async.wait_group 1;")

#define LDSM_X4(r0, r1, r2, r3, addr) \
    asm volatile("ldmatrix.sync.aligned.m8n8.x4.shared.b16 {%0,%1,%2,%3}, [%4];" \
        : "=r"(r0), "=r"(r1), "=r"(r2), "=r"(r3) : "r"(addr))

#define MMA_BF16(d, a, b0, b1) \
    asm volatile("mma.sync.aligned.m16n8k16.row.col.f32.bf16.bf16.f32 " \
        "{%0,%1,%2,%3}, {%4,%5,%6,%7}, {%8,%9}, {%0,%1,%2,%3};" \
        : "+f"((d)[0]), "+f"((d)[1]), "+f"((d)[2]), "+f"((d)[3]) \
        : "r"((a)[0]), "r"((a)[1]), "r"((a)[2]), "r"((a)[3]), "r"(b0), "r"(b1))

// ---------------- pipelined bf16x3 GEMM: C[M,N] = A[M,K] * B[N,K]^T ----------------
// operands pre-split (hi/lo bf16). 128x128 tile, BK=64, 2-stage cp.async pipeline.
// stage layout (64KB): Ah@0, Al@16K, Bh@32K, Bl@48K.  EPI: 0=write fp32, 1=softplus(+bias)
#define STAGE_B 65536
#define SMEM_B (2*STAGE_B)

template<int EPI>
__global__ void __launch_bounds__(256, 1) gemm_bs(
    const bf16* __restrict__ Ah, const bf16* __restrict__ Al, int lda,
    const bf16* __restrict__ Bh, const bf16* __restrict__ Bl, int ldb,
    float* __restrict__ C, int ldc, int N, int kbeg, int kend,
    size_t partStride, const float* __restrict__ bias)
{
    extern __shared__ __align__(16) char sm[];
    const uint32_t sbase = smem_u32(sm);
    const int tid = threadIdx.x;
    const int wid = tid >> 5;
    const int lane = tid & 31;
    const int m0 = blockIdx.y * 128;
    const int n0 = blockIdx.x * 128;
    C += (size_t)blockIdx.z * partStride;
    const int kb = kbeg + (int)blockIdx.z * (kend - kbeg);   // per-slice k window
    const int S = (kend - kbeg) >> 6;

    const int wm = (wid >> 1) * 32;
    const int wn = (wid & 1) * 64;
    const int a_r = lane & 15;
    const int a_c = (lane >> 4) * 8;
    const int b_r = (lane & 7) + ((lane >> 4) << 3);
    const int b_c = ((lane >> 3) & 1) * 8;

    const int lrow = tid >> 1;
    const int cb0 = (tid & 1) * 4;
    const bf16* agh = Ah + (size_t)(m0 + lrow) * lda + kb;
    const bf16* agl = Al + (size_t)(m0 + lrow) * lda + kb;
    const bf16* bgh = Bh + (size_t)(n0 + lrow) * ldb + kb;
    const bf16* bgl = Bl + (size_t)(n0 + lrow) * ldb + kb;
    const uint32_t bsz = ((n0 + lrow) < N) ? 16u : 0u;

    auto load_stage = [&](int s) {
        const uint32_t st = sbase + (uint32_t)(s & 1) * STAGE_B;
        const int k0 = s << 6;
#pragma unroll
        for (int j = 0; j < 4; j++) {
            int c16 = cb0 + j;
            uint32_t sw = st + swz(lrow * 128 + c16 * 16);
            CP_ASYNC(sw,          agh + k0 + c16 * 8, 16u);
            CP_ASYNC(sw + 16384u, agl + k0 + c16 * 8, 16u);
            CP_ASYNC(sw + 32768u, bgh + k0 + c16 * 8, bsz);
            CP_ASYNC(sw + 49152u, bgl + k0 + c16 * 8, bsz);
        }
    };

    float acc[2][8][4];
#pragma unroll
    for (int i = 0; i < 2; i++)
#pragma unroll
        for (int j = 0; j < 8; j++)
#pragma unroll
            for (int k = 0; k < 4; k++) acc[i][j][k] = 0.f;

    load_stage(0); CP_COMMIT();
    if (S > 1) load_stage(1);
    CP_COMMIT();

    for (int s = 0; s < S; s++) {
        CP_WAIT1();
        __syncthreads();
        const uint32_t st = sbase + (uint32_t)(s & 1) * STAGE_B;
#pragma unroll
        for (int ks = 0; ks < 4; ks++) {
            uint32_t ah[2][4], al[2][4];
#pragma unroll
            for (int mi = 0; mi < 2; mi++) {
                uint32_t ad = st + swz((wm + mi * 16 + a_r) * 128 + (ks * 16 + a_c) * 2);
                LDSM_X4(ah[mi][0], ah[mi][1], ah[mi][2], ah[mi][3], ad);
                LDSM_X4(al[mi][0], al[mi][1], al[mi][2], al[mi][3], ad + 16384u);
            }
            uint32_t bh[4][4];
#pragma unroll
            for (int bj = 0; bj < 4; bj++) {
                uint32_t bd = st + 32768u + swz((wn + bj * 16 + b_r) * 128 + (ks * 16 + b_c) * 2);
                LDSM_X4(bh[bj][0], bh[bj][1], bh[bj][2], bh[bj][3], bd);
            }
#pragma unroll
            for (int mi = 0; mi < 2; mi++)
#pragma unroll
                for (int nj = 0; nj < 8; nj++)
                    MMA_BF16(acc[mi][nj], ah[mi], bh[nj >> 1][(nj & 1) * 2], bh[nj >> 1][(nj & 1) * 2 + 1]);
#pragma unroll
            for (int mi = 0; mi < 2; mi++)
#pragma unroll
                for (int nj = 0; nj < 8; nj++)
                    MMA_BF16(acc[mi][nj], al[mi], bh[nj >> 1][(nj & 1) * 2], bh[nj >> 1][(nj & 1) * 2 + 1]);
            uint32_t bl[4][4];
#pragma unroll
            for (int bj = 0; bj < 4; bj++) {
                uint32_t bd = st + 49152u + swz((wn + bj * 16 + b_r) * 128 + (ks * 16 + b_c) * 2);
                LDSM_X4(bl[bj][0], bl[bj][1], bl[bj][2], bl[bj][3], bd);
            }
#pragma unroll
            for (int mi = 0; mi < 2; mi++)
#pragma unroll
                for (int nj = 0; nj < 8; nj++)
                    MMA_BF16(acc[mi][nj], ah[mi], bl[nj >> 1][(nj & 1) * 2], bl[nj >> 1][(nj & 1) * 2 + 1]);
        }
        __syncthreads();
        if (s + 2 < S) load_stage(s + 2);
        CP_COMMIT();
    }

    const int gr = lane >> 2;
    const int tc = (lane & 3) * 2;
#pragma unroll
    for (int mi = 0; mi < 2; mi++) {
#pragma unroll
        for (int nj = 0; nj < 8; nj++) {
            int r = m0 + wm + mi * 16 + gr;
            int c = n0 + wn + nj * 8 + tc;
            if (c < N) {
                float v0 = acc[mi][nj][0], v1 = acc[mi][nj][1];
                float v2 = acc[mi][nj][2], v3 = acc[mi][nj][3];
                if (EPI == 1) {
                    float b0 = bias[c], b1 = bias[c + 1];
                    v0 += b0; v1 += b1; v2 += b0; v3 += b1;
                    v0 = (v0 > 20.f) ? v0 : log1pf(__expf(v0));
                    v1 = (v1 > 20.f) ? v1 : log1pf(__expf(v1));
                    v2 = (v2 > 20.f) ? v2 : log1pf(__expf(v2));
                    v3 = (v3 > 20.f) ? v3 : log1pf(__expf(v3));
                }
                float* p0 = C + (size_t)r * ldc + c;
                float* p1 = C + (size_t)(r + 8) * ldc + c;
                p0[0] = v0; p0[1] = v1;
                p1[0] = v2; p1[1] = v3;
            }
        }
    }
}

// ---------------- elementwise helpers ----------------
__device__ __forceinline__ void split1(float v, bf16& h, bf16& l) {
    h = __float2bfloat16(v);
    l = __float2bfloat16(v - __bfloat162float(h));
}

__global__ void split2(const float* __restrict__ in, bf16* __restrict__ h, bf16* __restrict__ l, int n) {
    int i = (blockIdx.x * blockDim.x + threadIdx.x) * 4;
    if (i < n) {
        float4 v = *(const float4*)(in + i);
        bf16 h0, l0, h1, l1, h2, l2, h3, l3;
        split1(v.x, h0, l0); split1(v.y, h1, l1);
        split1(v.z, h2, l2); split1(v.w, h3, l3);
        h[i] = h0; h[i+1] = h1; h[i+2] = h2; h[i+3] = h3;
        l[i] = l0; l[i+1] = l1; l[i+2] = l2; l[i+3] = l3;
    }
}

__global__ void pack_split_wcat(const float* __restrict__ Wf, const float* __restrict__ Wr) {
    int i = blockIdx.x * blockDim.x + threadIdx.x;   // Dz*E2
    int n = i >> 12;
    int k = i & 4095;
    float v = (k < DIz) ? Wf[n * DIz + k] : Wr[n * DIz + (k - DIz)];
    split1(v, g_wch[i], g_wcl[i]);
}

__global__ void prep_A(const float* __restrict__ Af, const float* __restrict__ Ar) {
    int i = blockIdx.x * blockDim.x + threadIdx.x;
    if (i < DIz * NS) {
        g_A0[i] = -expf(Af[i]);
        g_A1[i] = -expf(Ar[i]);
    }
}

// reduce split-K partials of x_dbl, write fp32 xd + bf16 split of first 64 cols
__global__ void reduce_xd() {
    int idx = blockIdx.x * blockDim.x + threadIdx.x;   // 2*BL*XD
    int dir = idx >= BL * XD;
    int j = dir ? idx - BL * XD : idx;
    const float* p = dir ? g_xdp1 : g_xdp0;
    float s = 0.f;
#pragma unroll
    for (int k = 0; k < KSPLIT; k++) s += p[k * (BL * XD) + j];
    (dir ? g_xd1 : g_xd0)[j] = s;
    int col = j % XD;
    if (col < RK) {
        int row = j / XD;
        bf16 h, l; split1(s, h, l);
        (dir ? g_xdh1 : g_xdh0)[row * RK + col] = h;
        (dir ? g_xdl1 : g_xdl0)[row * RK + col] = l;
    }
}

// ---------------- causal depthwise conv (K=4) + SiLU, emits fp32 + hi/lo ----------------
__global__ void conv_silu(const float* __restrict__ Wf, const float* __restrict__ bf,
                          const float* __restrict__ Wr, const float* __restrict__ br)
{
    int idx = blockIdx.x * blockDim.x + threadIdx.x;
    int d = idx & (DIz - 1);
    int t = idx >> 11;
    int m = t & (Lz - 1);
    t >>= 10;
    int b = t & 1;
    int dir = t >> 1;

    const float* xz = dir ? g_xz1 : g_xz0;
    const float* W  = dir ? Wr : Wf;
    const float* bc = dir ? br : bf;

    float acc = bc[d];
#pragma unroll
    for (int k = 0; k < 4; k++) {
        int mp = m - 3 + k;
        if (mp >= 0) {
            int orig = dir ? (Lz - 1 - mp) : mp;
            acc = fmaf(W[d * 4 + k], xz[((b << 10) + orig) * E2 + d], acc);
        }
    }
    float s = acc / (1.f + __expf(-acc));
    int o = ((b << 10) + m) * DIz + d;
    (dir ? g_xc1 : g_xc0)[o] = s;
    bf16 h, l; split1(s, h, l);
    (dir ? g_xch1 : g_xch0)[o] = h;
    (dir ? g_xcl1 : g_xcl0)[o] = l;
}

// ---------------- selective scan: emits y split directly ----------------
__global__ void __launch_bounds__(256) scan_kernel(const float* __restrict__ Dskf,
                                                   const float* __restrict__ Dskr)
{
    int gw = (blockIdx.x * blockDim.x + threadIdx.x) >> 5;
    int lane = threadIdx.x & 31;
    int dir = gw >> 11;
    int rem = gw & 2047;
    int c = (rem << 1) | (lane >> 4);
    int b = c >> 11;
    int d = c & 2047;
    int n = lane & 15;

    const float* dt = dir ? g_dt1 : g_dt0;
    const float* xc = dir ? g_xc1 : g_xc0;
    const float* xd = dir ? g_xd1 : g_xd0;
    const float* xz = dir ? g_xz1 : g_xz0;
    const float* Aa = dir ? g_A1  : g_A0;

    float An = Aa[d * NS + n];
    float Dd = (dir ? Dskr : Dskf)[d];

    int base = b * Lz;
    const float* dtp = dt + (size_t)base * DIz + d;
    const float* up  = xc + (size_t)base * DIz + d;
    const float* bcp = xd + (size_t)base * XD + 64 + n;

    int orig0 = dir ? (Lz - 1) : 0;
    int dz = dir ? -E2 : E2;
    int zoff = (base + orig0) * E2 + DIz + d;
    int yoff = (base + orig0) * E2 + dir * DIz + d;

    float h = 0.f;
    for (int m = 0; m < Lz; m++) {
        float delta = *dtp;
        float u = *up;
        float Bv = bcp[0];
        float Cv = bcp[16];
        float a = __expf(delta * An);
        h = fmaf(a, h, delta * u * Bv);
        float s = Cv * h;
        s += __shfl_xor_sync(0xffffffffu, s, 1, 16);
        s += __shfl_xor_sync(0xffffffffu, s, 2, 16);
        s += __shfl_xor_sync(0xffffffffu, s, 4, 16);
        s += __shfl_xor_sync(0xffffffffu, s, 8, 16);
        if (n == 0) {
            float y = fmaf(u, Dd, s);
            float z = xz[zoff];
            y *= z / (1.f + __expf(-z));
            bf16 hh, ll; split1(y, hh, ll);
            g_yh[yoff] = hh;
            g_yl[yoff] = ll;
        }
        dtp += DIz; up += DIz; bcp += XD; zoff += dz; yoff += dz;
    }
}

// ---------------- launch ----------------
extern "C" void kernel_launch(void* const* d_in, const int* in_sizes, int n_in,
                              void* d_out, int out_size)
{
    (void)in_sizes; (void)n_in; (void)out_size;
    const float* x       = (const float*)d_in[0];
    const float* Win_f   = (const float*)d_in[1];
    const float* Wconv_f = (const float*)d_in[2];
    const float* bconv_f = (const float*)d_in[3];
    const float* Wx_f    = (const float*)d_in[4];
    const float* Wdt_f   = (const float*)d_in[5];
    const float* bdt_f   = (const float*)d_in[6];
    const float* Alog_f  = (const float*)d_in[7];
    const float* Dsk_f   = (const float*)d_in[8];
    const float* Wout_f  = (const float*)d_in[9];
    const float* Win_r   = (const float*)d_in[10];
    const float* Wconv_r = (const float*)d_in[11];
    const float* bconv_r = (const float*)d_in[12];
    const float* Wx_r    = (const float*)d_in[13];
    const float* Wdt_r   = (const float*)d_in[14];
    const float* bdt_r   = (const float*)d_in[15];
    const float* Alog_r  = (const float*)d_in[16];
    const float* Dsk_r   = (const float*)d_in[17];
    const float* Wout_r  = (const float*)d_in[18];
    float* out = (float*)d_out;

    // device pointers to globals
    float *xz0, *xz1, *dt0, *dt1, *xdp0, *xdp1;
    bf16 *xh, *xl, *w1fh, *w1fl, *w1rh, *w1rl, *xch0, *xcl0, *xch1, *xcl1;
    bf16 *wxfh, *wxfl, *wxrh, *wxrl, *wdtfh, *wdtfl, *wdtrh, *wdtrl;
    bf16 *xdh0, *xdl0, *xdh1, *xdl1, *yh, *yl, *wch, *wcl;
    cudaGetSymbolAddress((void**)&xz0, g_xz0);
    cudaGetSymbolAddress((void**)&xz1, g_xz1);
    cudaGetSymbolAddress((void**)&dt0, g_dt0);
    cudaGetSymbolAddress((void**)&dt1, g_dt1);
    cudaGetSymbolAddress((void**)&xdp0, g_xdp0);
    cudaGetSymbolAddress((void**)&xdp1, g_xdp1);
    cudaGetSymbolAddress((void**)&xh, g_xh);     cudaGetSymbolAddress((void**)&xl, g_xl);
    cudaGetSymbolAddress((void**)&w1fh, g_w1fh); cudaGetSymbolAddress((void**)&w1fl, g_w1fl);
    cudaGetSymbolAddress((void**)&w1rh, g_w1rh); cudaGetSymbolAddress((void**)&w1rl, g_w1rl);
    cudaGetSymbolAddress((void**)&xch0, g_xch0); cudaGetSymbolAddress((void**)&xcl0, g_xcl0);
    cudaGetSymbolAddress((void**)&xch1, g_xch1); cudaGetSymbolAddress((void**)&xcl1, g_xcl1);
    cudaGetSymbolAddress((void**)&wxfh, g_wxfh); cudaGetSymbolAddress((void**)&wxfl, g_wxfl);
    cudaGetSymbolAddress((void**)&wxrh, g_wxrh); cudaGetSymbolAddress((void**)&wxrl, g_wxrl);
    cudaGetSymbolAddress((void**)&wdtfh, g_wdtfh); cudaGetSymbolAddress((void**)&wdtfl, g_wdtfl);
    cudaGetSymbolAddress((void**)&wdtrh, g_wdtrh); cudaGetSymbolAddress((void**)&wdtrl, g_wdtrl);
    cudaGetSymbolAddress((void**)&xdh0, g_xdh0); cudaGetSymbolAddress((void**)&xdl0, g_xdl0);
    cudaGetSymbolAddress((void**)&xdh1, g_xdh1); cudaGetSymbolAddress((void**)&xdl1, g_xdl1);
    cudaGetSymbolAddress((void**)&yh, g_yh);     cudaGetSymbolAddress((void**)&yl, g_yl);
    cudaGetSymbolAddress((void**)&wch, g_wch);   cudaGetSymbolAddress((void**)&wcl, g_wcl);

    cudaFuncSetAttribute(gemm_bs<0>, cudaFuncAttributeMaxDynamicSharedMemorySize, SMEM_B);
    cudaFuncSetAttribute(gemm_bs<1>, cudaFuncAttributeMaxDynamicSharedMemorySize, SMEM_B);

    // ---- operand splits ----
    split2<<<(BL*Dz/4 + 255)/256, 256>>>(x, xh, xl, BL*Dz);
    split2<<<(E2*Dz/4 + 255)/256, 256>>>(Win_f, w1fh, w1fl, E2*Dz);
    split2<<<(E2*Dz/4 + 255)/256, 256>>>(Win_r, w1rh, w1rl, E2*Dz);
    split2<<<(XD*DIz/4 + 255)/256, 256>>>(Wx_f, wxfh, wxfl, XD*DIz);
    split2<<<(XD*DIz/4 + 255)/256, 256>>>(Wx_r, wxrh, wxrl, XD*DIz);
    split2<<<(DIz*RK/4 + 255)/256, 256>>>(Wdt_f, wdtfh, wdtfl, DIz*RK);
    split2<<<(DIz*RK/4 + 255)/256, 256>>>(Wdt_r, wdtrh, wdtrl, DIz*RK);
    pack_split_wcat<<<(Dz*E2 + 255)/256, 256>>>(Wout_f, Wout_r);
    prep_A<<<(DIz*NS + 255)/256, 256>>>(Alog_f, Alog_r);

    // ---- GEMM1: xz = x @ Win^T  (M=2048, N=4096, K=1024) ----
    gemm_bs<0><<<dim3(E2/128, BL/128, 1), 256, SMEM_B>>>(xh, xl, Dz, w1fh, w1fl, Dz, xz0, E2, E2, 0, Dz, 0, nullptr);
    gemm_bs<0><<<dim3(E2/128, BL/128, 1), 256, SMEM_B>>>(xh, xl, Dz, w1rh, w1rl, Dz, xz1, E2, E2, 0, Dz, 0, nullptr);

    conv_silu<<<(2*BL*DIz)/256, 256>>>(Wconv_f, bconv_f, Wconv_r, bconv_r);

    // ---- GEMM2 (split-K x8): x_dbl partials = xc @ Wx^T  (M=2048, N=96, K=2048) ----
    gemm_bs<0><<<dim3(1, BL/128, KSPLIT), 256, SMEM_B>>>(xch0, xcl0, DIz, wxfh, wxfl, DIz, xdp0, XD, XD, 0, DIz/KSPLIT, (size_t)BL*XD, nullptr);
    gemm_bs<0><<<dim3(1, BL/128, KSPLIT), 256, SMEM_B>>>(xch1, xcl1, DIz, wxrh, wxrl, DIz, xdp1, XD, XD, 0, DIz/KSPLIT, (size_t)BL*XD, nullptr);
    reduce_xd<<<(2*BL*XD + 255)/256, 256>>>();

    // ---- GEMM3: dt = softplus(x_dbl[:, :64] @ Wdt^T + bdt)  (M=2048, N=2048, K=64) ----
    gemm_bs<1><<<dim3(DIz/128, BL/128, 1), 256, SMEM_B>>>(xdh0, xdl0, RK, wdtfh, wdtfl, RK, dt0, DIz, DIz, 0, RK, 0, bdt_f);
    gemm_bs<1><<<dim3(DIz/128, BL/128, 1), 256, SMEM_B>>>(xdh1, xdl1, RK, wdtrh, wdtrl, RK, dt1, DIz, DIz, 0, RK, 0, bdt_r);

    scan_kernel<<<512, 256>>>(Dsk_f, Dsk_r);

    // ---- GEMM4: out = ycat @ wcat^T  (M=2048, N=1024, K=4096) ----
    gemm_bs<0><<<dim3(Dz/128, BL/128, 1), 256, SMEM_B>>>(yh, yl, E2, wch, wcl, E2, out, Dz, Dz, 0, E2, 0, nullptr);
}

// round 8
// speedup vs baseline: 1.6492x; 1.0259x over previous
#include <cuda_runtime.h>
#include <cuda_bf16.h>
#include <math.h>
#include <stdint.h>

#define Bz 2
#define Lz 1024
#define Dz 1024
#define DIz 2048
#define E2 4096
#define RK 64
#define NS 16
#define XD 96
#define BL (Bz*Lz)
#define KSPLIT 8

typedef __nv_bfloat16 bf16;

// ---------------- scratch ----------------
__device__ float g_xz0[BL*E2];
__device__ float g_xz1[BL*E2];
__device__ float g_xc0[BL*DIz];
__device__ float g_xc1[BL*DIz];
__device__ float g_xd0[BL*XD];
__device__ float g_xd1[BL*XD];
__device__ float g_xdp0[KSPLIT*BL*XD];
__device__ float g_xdp1[KSPLIT*BL*XD];
__device__ float g_dt0[BL*DIz];
__device__ float g_dt1[BL*DIz];
__device__ float g_A0[DIz*NS];
__device__ float g_A1[DIz*NS];

__device__ bf16 g_xh[BL*Dz],    g_xl[BL*Dz];
__device__ bf16 g_w1fh[E2*Dz],  g_w1fl[E2*Dz];
__device__ bf16 g_w1rh[E2*Dz],  g_w1rl[E2*Dz];
__device__ bf16 g_xch0[BL*DIz], g_xcl0[BL*DIz];
__device__ bf16 g_xch1[BL*DIz], g_xcl1[BL*DIz];
__device__ bf16 g_wxfh[XD*DIz], g_wxfl[XD*DIz];
__device__ bf16 g_wxrh[XD*DIz], g_wxrl[XD*DIz];
__device__ bf16 g_wdtfh[DIz*RK], g_wdtfl[DIz*RK];
__device__ bf16 g_wdtrh[DIz*RK], g_wdtrl[DIz*RK];
__device__ bf16 g_xdh0[BL*RK],  g_xdl0[BL*RK];
__device__ bf16 g_xdh1[BL*RK],  g_xdl1[BL*RK];
__device__ bf16 g_yh[BL*E2],    g_yl[BL*E2];
__device__ bf16 g_wch[Dz*E2],   g_wcl[Dz*E2];

__device__ __forceinline__ uint32_t smem_u32(const void* p) {
    uint32_t a;
    asm("{ .reg .u64 t; cvta.to.shared.u64 t, %1; cvt.u32.u64 %0, t; }" : "=r"(a) : "l"(p));
    return a;
}
__device__ __forceinline__ uint32_t swz(uint32_t o) { return o ^ (((o >> 7) & 7) << 4); }

#define CP_ASYNC(dst, src, sz) \
    asm volatile("cp.async.cg.shared.global [%0], [%1], 16, %2;" :: "r"(dst), "l"(src), "r"(sz))
#define CP_COMMIT() asm volatile("cp.async.commit_group;")
#define CP_WAIT2()  asm volatile("cp.async.wait_group 2;")

#define LDSM_X4(r0, r1, r2, r3, addr) \
    asm volatile("ldmatrix.sync.aligned.m8n8.x4.shared.b16 {%0,%1,%2,%3}, [%4];" \
        : "=r"(r0), "=r"(r1), "=r"(r2), "=r"(r3) : "r"(addr))

#define MMA_BF16(d, a, b0, b1) \
    asm volatile("mma.sync.aligned.m16n8k16.row.col.f32.bf16.bf16.f32 " \
        "{%0,%1,%2,%3}, {%4,%5,%6,%7}, {%8,%9}, {%0,%1,%2,%3};" \
        : "+f"((d)[0]), "+f"((d)[1]), "+f"((d)[2]), "+f"((d)[3]) \
        : "r"((a)[0]), "r"((a)[1]), "r"((a)[2]), "r"((a)[3]), "r"(b0), "r"(b1))

struct GemmP {
    const bf16* Ah[2]; const bf16* Al[2];
    const bf16* Bh[2]; const bf16* Bl[2];
    float* C[2]; const float* bias[2];
};

// ---------------- pipelined dual bf16x3 GEMM: C[M,N] = A[M,K] * B[N,K]^T ----------------
// 128x128 tile, BK=64, 3-stage cp.async pipeline.
// stage layout (64KB): Ah@0, Al@16K, Bh@32K, Bl@48K.
#define STAGE_B 65536
#define SMEM_B (3*STAGE_B)

template<int EPI>   // 0 = write fp32, 1 = softplus(acc + bias[col])
__global__ void __launch_bounds__(256, 1) gemm_bs(
    GemmP gp, int lda, int ldb, int ldc, int N,
    int klen, int nsl, size_t partStride)
{
    extern __shared__ __align__(16) char sm[];
    const uint32_t sbase = smem_u32(sm);
    const int tid = threadIdx.x;
    const int wid = tid >> 5;
    const int lane = tid & 31;
    const int m0 = blockIdx.y * 128;
    const int n0 = blockIdx.x * 128;
    const int zz = blockIdx.z;
    const int dir = zz / nsl;
    const int slice = zz - dir * nsl;
    const int kb = slice * klen;
    const int S = klen >> 6;

    const bf16* __restrict__ Ah = gp.Ah[dir];
    const bf16* __restrict__ Al = gp.Al[dir];
    const bf16* __restrict__ Bh = gp.Bh[dir];
    const bf16* __restrict__ Bl = gp.Bl[dir];
    float* __restrict__ C = gp.C[dir] + (size_t)slice * partStride;
    const float* __restrict__ bias = gp.bias[dir];

    const int wm = (wid >> 1) * 32;
    const int wn = (wid & 1) * 64;
    const int a_r = lane & 15;
    const int a_c = (lane >> 4) * 8;
    const int b_r = (lane & 7) + ((lane >> 4) << 3);
    const int b_c = ((lane >> 3) & 1) * 8;

    const int lrow = tid >> 1;
    const int cb0 = (tid & 1) * 4;
    const bf16* agh = Ah + (size_t)(m0 + lrow) * lda + kb;
    const bf16* agl = Al + (size_t)(m0 + lrow) * lda + kb;
    const bf16* bgh = Bh + (size_t)(n0 + lrow) * ldb + kb;
    const bf16* bgl = Bl + (size_t)(n0 + lrow) * ldb + kb;
    const uint32_t bsz = ((n0 + lrow) < N) ? 16u : 0u;

    auto load_stage = [&](int s) {
        const uint32_t st = sbase + (uint32_t)(s % 3) * STAGE_B;
        const int k0 = s << 6;
#pragma unroll
        for (int j = 0; j < 4; j++) {
            int c16 = cb0 + j;
            uint32_t sw = st + swz(lrow * 128 + c16 * 16);
            CP_ASYNC(sw,          agh + k0 + c16 * 8, 16u);
            CP_ASYNC(sw + 16384u, agl + k0 + c16 * 8, 16u);
            CP_ASYNC(sw + 32768u, bgh + k0 + c16 * 8, bsz);
            CP_ASYNC(sw + 49152u, bgl + k0 + c16 * 8, bsz);
        }
    };

    float acc[2][8][4];
#pragma unroll
    for (int i = 0; i < 2; i++)
#pragma unroll
        for (int j = 0; j < 8; j++)
#pragma unroll
            for (int k = 0; k < 4; k++) acc[i][j][k] = 0.f;

    load_stage(0); CP_COMMIT();
    if (S > 1) load_stage(1);
    CP_COMMIT();
    if (S > 2) load_stage(2);
    CP_COMMIT();

    for (int s = 0; s < S; s++) {
        CP_WAIT2();
        __syncthreads();
        const uint32_t st = sbase + (uint32_t)(s % 3) * STAGE_B;
#pragma unroll
        for (int ks = 0; ks < 4; ks++) {
            uint32_t ah[2][4], al[2][4];
#pragma unroll
            for (int mi = 0; mi < 2; mi++) {
                uint32_t ad = st + swz((wm + mi * 16 + a_r) * 128 + (ks * 16 + a_c) * 2);
                LDSM_X4(ah[mi][0], ah[mi][1], ah[mi][2], ah[mi][3], ad);
                LDSM_X4(al[mi][0], al[mi][1], al[mi][2], al[mi][3], ad + 16384u);
            }
#pragma unroll
            for (int bj = 0; bj < 4; bj++) {
                uint32_t bh[4], bl[4];
                uint32_t bd = st + swz((wn + bj * 16 + b_r) * 128 + (ks * 16 + b_c) * 2);
                LDSM_X4(bh[0], bh[1], bh[2], bh[3], bd + 32768u);
                LDSM_X4(bl[0], bl[1], bl[2], bl[3], bd + 49152u);
                const int n0j = 2 * bj;
#pragma unroll
                for (int mi = 0; mi < 2; mi++) {
                    MMA_BF16(acc[mi][n0j],     ah[mi], bh[0], bh[1]);
                    MMA_BF16(acc[mi][n0j + 1], ah[mi], bh[2], bh[3]);
                }
#pragma unroll
                for (int mi = 0; mi < 2; mi++) {
                    MMA_BF16(acc[mi][n0j],     al[mi], bh[0], bh[1]);
                    MMA_BF16(acc[mi][n0j + 1], al[mi], bh[2], bh[3]);
                }
#pragma unroll
                for (int mi = 0; mi < 2; mi++) {
                    MMA_BF16(acc[mi][n0j],     ah[mi], bl[0], bl[1]);
                    MMA_BF16(acc[mi][n0j + 1], ah[mi], bl[2], bl[3]);
                }
            }
        }
        __syncthreads();
        if (s + 3 < S) load_stage(s + 3);
        CP_COMMIT();
    }

    const int gr = lane >> 2;
    const int tc = (lane & 3) * 2;
#pragma unroll
    for (int mi = 0; mi < 2; mi++) {
#pragma unroll
        for (int nj = 0; nj < 8; nj++) {
            int r = m0 + wm + mi * 16 + gr;
            int c = n0 + wn + nj * 8 + tc;
            if (c < N) {
                float v0 = acc[mi][nj][0], v1 = acc[mi][nj][1];
                float v2 = acc[mi][nj][2], v3 = acc[mi][nj][3];
                if (EPI == 1) {
                    float b0 = bias[c], b1 = bias[c + 1];
                    v0 += b0; v1 += b1; v2 += b0; v3 += b1;
                    v0 = (v0 > 20.f) ? v0 : log1pf(__expf(v0));
                    v1 = (v1 > 20.f) ? v1 : log1pf(__expf(v1));
                    v2 = (v2 > 20.f) ? v2 : log1pf(__expf(v2));
                    v3 = (v3 > 20.f) ? v3 : log1pf(__expf(v3));
                }
                float* p0 = C + (size_t)r * ldc + c;
                float* p1 = C + (size_t)(r + 8) * ldc + c;
                p0[0] = v0; p0[1] = v1;
                p1[0] = v2; p1[1] = v3;
            }
        }
    }
}

// ---------------- elementwise helpers ----------------
__device__ __forceinline__ void split1(float v, bf16& h, bf16& l) {
    h = __float2bfloat16(v);
    l = __float2bfloat16(v - __bfloat162float(h));
}

__global__ void split_single(const float* __restrict__ in, bf16* __restrict__ h, bf16* __restrict__ l, int n) {
    int i = (blockIdx.x * blockDim.x + threadIdx.x) * 4;
    if (i < n) {
        float4 v = *(const float4*)(in + i);
        bf16 h0, l0, h1, l1, h2, l2, h3, l3;
        split1(v.x, h0, l0); split1(v.y, h1, l1);
        split1(v.z, h2, l2); split1(v.w, h3, l3);
        h[i] = h0; h[i+1] = h1; h[i+2] = h2; h[i+3] = h3;
        l[i] = l0; l[i+1] = l1; l[i+2] = l2; l[i+3] = l3;
    }
}

__global__ void split_pair(const float* __restrict__ a, const float* __restrict__ b,
                           bf16* __restrict__ ha, bf16* __restrict__ la,
                           bf16* __restrict__ hb, bf16* __restrict__ lb, int n) {
    int i = (blockIdx.x * blockDim.x + threadIdx.x) * 4;
    const float* src; bf16 *dh, *dl; int j;
    if (i < n) { src = a; dh = ha; dl = la; j = i; }
    else if (i < 2 * n) { src = b; dh = hb; dl = lb; j = i - n; }
    else return;
    float4 v = *(const float4*)(src + j);
    bf16 h0, l0, h1, l1, h2, l2, h3, l3;
    split1(v.x, h0, l0); split1(v.y, h1, l1);
    split1(v.z, h2, l2); split1(v.w, h3, l3);
    dh[j] = h0; dh[j+1] = h1; dh[j+2] = h2; dh[j+3] = h3;
    dl[j] = l0; dl[j+1] = l1; dl[j+2] = l2; dl[j+3] = l3;
}

// wcat pack+split, and prep_A folded in
__global__ void misc_prep(const float* __restrict__ Wf, const float* __restrict__ Wr,
                          const float* __restrict__ Af, const float* __restrict__ Ar) {
    int i = blockIdx.x * blockDim.x + threadIdx.x;   // Dz*E2
    int n = i >> 12;
    int k = i & 4095;
    float v = (k < DIz) ? Wf[n * DIz + k] : Wr[n * DIz + (k - DIz)];
    split1(v, g_wch[i], g_wcl[i]);
    if (i < DIz * NS) {
        g_A0[i] = -expf(Af[i]);
        g_A1[i] = -expf(Ar[i]);
    }
}

// reduce split-K partials of x_dbl, write fp32 xd + bf16 split of first 64 cols
__global__ void reduce_xd() {
    int idx = blockIdx.x * blockDim.x + threadIdx.x;   // 2*BL*XD
    int dir = idx >= BL * XD;
    int j = dir ? idx - BL * XD : idx;
    const float* p = dir ? g_xdp1 : g_xdp0;
    float s = 0.f;
#pragma unroll
    for (int k = 0; k < KSPLIT; k++) s += p[k * (BL * XD) + j];
    (dir ? g_xd1 : g_xd0)[j] = s;
    int col = j % XD;
    if (col < RK) {
        int row = j / XD;
        bf16 h, l; split1(s, h, l);
        (dir ? g_xdh1 : g_xdh0)[row * RK + col] = h;
        (dir ? g_xdl1 : g_xdl0)[row * RK + col] = l;
    }
}

// ---------------- causal depthwise conv (K=4) + SiLU, emits fp32 + hi/lo ----------------
__global__ void conv_silu(const float* __restrict__ Wf, const float* __restrict__ bf,
                          const float* __restrict__ Wr, const float* __restrict__ br)
{
    int idx = blockIdx.x * blockDim.x + threadIdx.x;
    int d = idx & (DIz - 1);
    int t = idx >> 11;
    int m = t & (Lz - 1);
    t >>= 10;
    int b = t & 1;
    int dir = t >> 1;

    const float* xz = dir ? g_xz1 : g_xz0;
    const float* W  = dir ? Wr : Wf;
    const float* bc = dir ? br : bf;

    float acc = bc[d];
#pragma unroll
    for (int k = 0; k < 4; k++) {
        int mp = m - 3 + k;
        if (mp >= 0) {
            int orig = dir ? (Lz - 1 - mp) : mp;
            acc = fmaf(W[d * 4 + k], xz[((b << 10) + orig) * E2 + d], acc);
        }
    }
    float s = acc / (1.f + __expf(-acc));
    int o = ((b << 10) + m) * DIz + d;
    (dir ? g_xc1 : g_xc0)[o] = s;
    bf16 h, l; split1(s, h, l);
    (dir ? g_xch1 : g_xch0)[o] = h;
    (dir ? g_xcl1 : g_xcl0)[o] = l;
}

// ---------------- selective scan: emits y split directly ----------------
__global__ void __launch_bounds__(256) scan_kernel(const float* __restrict__ Dskf,
                                                   const float* __restrict__ Dskr)
{
    int gw = (blockIdx.x * blockDim.x + threadIdx.x) >> 5;
    int lane = threadIdx.x & 31;
    int dir = gw >> 11;
    int rem = gw & 2047;
    int c = (rem << 1) | (lane >> 4);
    int b = c >> 11;
    int d = c & 2047;
    int n = lane & 15;

    const float* dt = dir ? g_dt1 : g_dt0;
    const float* xc = dir ? g_xc1 : g_xc0;
    const float* xd = dir ? g_xd1 : g_xd0;
    const float* xz = dir ? g_xz1 : g_xz0;
    const float* Aa = dir ? g_A1  : g_A0;

    float An = Aa[d * NS + n];
    float Dd = (dir ? Dskr : Dskf)[d];

    int base = b * Lz;
    const float* dtp = dt + (size_t)base * DIz + d;
    const float* up  = xc + (size_t)base * DIz + d;
    const float* bcp = xd + (size_t)base * XD + 64 + n;

    int orig0 = dir ? (Lz - 1) : 0;
    int dz = dir ? -E2 : E2;
    int zoff = (base + orig0) * E2 + DIz + d;
    int yoff = (base + orig0) * E2 + dir * DIz + d;

    float h = 0.f;
    for (int m = 0; m < Lz; m++) {
        float delta = *dtp;
        float u = *up;
        float Bv = bcp[0];
        float Cv = bcp[16];
        float a = __expf(delta * An);
        h = fmaf(a, h, delta * u * Bv);
        float s = Cv * h;
        s += __shfl_xor_sync(0xffffffffu, s, 1, 16);
        s += __shfl_xor_sync(0xffffffffu, s, 2, 16);
        s += __shfl_xor_sync(0xffffffffu, s, 4, 16);
        s += __shfl_xor_sync(0xffffffffu, s, 8, 16);
        if (n == 0) {
            float y = fmaf(u, Dd, s);
            float z = xz[zoff];
            y *= z / (1.f + __expf(-z));
            bf16 hh, ll; split1(y, hh, ll);
            g_yh[yoff] = hh;
            g_yl[yoff] = ll;
        }
        dtp += DIz; up += DIz; bcp += XD; zoff += dz; yoff += dz;
    }
}

// ---------------- launch ----------------
extern "C" void kernel_launch(void* const* d_in, const int* in_sizes, int n_in,
                              void* d_out, int out_size)
{
    (void)in_sizes; (void)n_in; (void)out_size;
    const float* x       = (const float*)d_in[0];
    const float* Win_f   = (const float*)d_in[1];
    const float* Wconv_f = (const float*)d_in[2];
    const float* bconv_f = (const float*)d_in[3];
    const float* Wx_f    = (const float*)d_in[4];
    const float* Wdt_f   = (const float*)d_in[5];
    const float* bdt_f   = (const float*)d_in[6];
    const float* Alog_f  = (const float*)d_in[7];
    const float* Dsk_f   = (const float*)d_in[8];
    const float* Wout_f  = (const float*)d_in[9];
    const float* Win_r   = (const float*)d_in[10];
    const float* Wconv_r = (const float*)d_in[11];
    const float* bconv_r = (const float*)d_in[12];
    const float* Wx_r    = (const float*)d_in[13];
    const float* Wdt_r   = (const float*)d_in[14];
    const float* bdt_r   = (const float*)d_in[15];
    const float* Alog_r  = (const float*)d_in[16];
    const float* Dsk_r   = (const float*)d_in[17];
    const float* Wout_r  = (const float*)d_in[18];
    float* out = (float*)d_out;

    float *xz0, *xz1, *dt0, *dt1, *xdp0, *xdp1;
    bf16 *xh, *xl, *w1fh, *w1fl, *w1rh, *w1rl, *xch0, *xcl0, *xch1, *xcl1;
    bf16 *wxfh, *wxfl, *wxrh, *wxrl, *wdtfh, *wdtfl, *wdtrh, *wdtrl;
    bf16 *xdh0, *xdl0, *xdh1, *xdl1, *yh, *yl, *wch, *wcl;
    cudaGetSymbolAddress((void**)&xz0, g_xz0);
    cudaGetSymbolAddress((void**)&xz1, g_xz1);
    cudaGetSymbolAddress((void**)&dt0, g_dt0);
    cudaGetSymbolAddress((void**)&dt1, g_dt1);
    cudaGetSymbolAddress((void**)&xdp0, g_xdp0);
    cudaGetSymbolAddress((void**)&xdp1, g_xdp1);
    cudaGetSymbolAddress((void**)&xh, g_xh);     cudaGetSymbolAddress((void**)&xl, g_xl);
    cudaGetSymbolAddress((void**)&w1fh, g_w1fh); cudaGetSymbolAddress((void**)&w1fl, g_w1fl);
    cudaGetSymbolAddress((void**)&w1rh, g_w1rh); cudaGetSymbolAddress((void**)&w1rl, g_w1rl);
    cudaGetSymbolAddress((void**)&xch0, g_xch0); cudaGetSymbolAddress((void**)&xcl0, g_xcl0);
    cudaGetSymbolAddress((void**)&xch1, g_xch1); cudaGetSymbolAddress((void**)&xcl1, g_xcl1);
    cudaGetSymbolAddress((void**)&wxfh, g_wxfh); cudaGetSymbolAddress((void**)&wxfl, g_wxfl);
    cudaGetSymbolAddress((void**)&wxrh, g_wxrh); cudaGetSymbolAddress((void**)&wxrl, g_wxrl);
    cudaGetSymbolAddress((void**)&wdtfh, g_wdtfh); cudaGetSymbolAddress((void**)&wdtfl, g_wdtfl);
    cudaGetSymbolAddress((void**)&wdtrh, g_wdtrh); cudaGetSymbolAddress((void**)&wdtrl, g_wdtrl);
    cudaGetSymbolAddress((void**)&xdh0, g_xdh0); cudaGetSymbolAddress((void**)&xdl0, g_xdl0);
    cudaGetSymbolAddress((void**)&xdh1, g_xdh1); cudaGetSymbolAddress((void**)&xdl1, g_xdl1);
    cudaGetSymbolAddress((void**)&yh, g_yh);     cudaGetSymbolAddress((void**)&yl, g_yl);
    cudaGetSymbolAddress((void**)&wch, g_wch);   cudaGetSymbolAddress((void**)&wcl, g_wcl);

    cudaFuncSetAttribute(gemm_bs<0>, cudaFuncAttributeMaxDynamicSharedMemorySize, SMEM_B);
    cudaFuncSetAttribute(gemm_bs<1>, cudaFuncAttributeMaxDynamicSharedMemorySize, SMEM_B);

    // ---- prep (5 launches so that launch #6 = merged GEMM1 for ncu -s 5 -c 1) ----
    split_single<<<(BL*Dz/4 + 255)/256, 256>>>(x, xh, xl, BL*Dz);
    split_pair<<<(2*E2*Dz/4 + 255)/256, 256>>>(Win_f, Win_r, w1fh, w1fl, w1rh, w1rl, E2*Dz);
    split_pair<<<(2*XD*DIz/4 + 255)/256, 256>>>(Wx_f, Wx_r, wxfh, wxfl, wxrh, wxrl, XD*DIz);
    split_pair<<<(2*DIz*RK/4 + 255)/256, 256>>>(Wdt_f, Wdt_r, wdtfh, wdtfl, wdtrh, wdtrl, DIz*RK);
    misc_prep<<<(Dz*E2 + 255)/256, 256>>>(Wout_f, Wout_r, Alog_f, Alog_r);

    // ---- GEMM1 (dual): xz = x @ Win^T  (M=2048, N=4096, K=1024) ----
    {
        GemmP gp{};
        gp.Ah[0] = xh;  gp.Ah[1] = xh;  gp.Al[0] = xl;  gp.Al[1] = xl;
        gp.Bh[0] = w1fh; gp.Bh[1] = w1rh; gp.Bl[0] = w1fl; gp.Bl[1] = w1rl;
        gp.C[0] = xz0;  gp.C[1] = xz1;
        gemm_bs<0><<<dim3(E2/128, BL/128, 2), 256, SMEM_B>>>(gp, Dz, Dz, E2, E2, Dz, 1, 0);
    }

    conv_silu<<<(2*BL*DIz)/256, 256>>>(Wconv_f, bconv_f, Wconv_r, bconv_r);

    // ---- GEMM2 (dual, split-K x8): x_dbl partials = xc @ Wx^T  (M=2048, N=96, K=2048) ----
    {
        GemmP gp{};
        gp.Ah[0] = xch0; gp.Ah[1] = xch1; gp.Al[0] = xcl0; gp.Al[1] = xcl1;
        gp.Bh[0] = wxfh; gp.Bh[1] = wxrh; gp.Bl[0] = wxfl; gp.Bl[1] = wxrl;
        gp.C[0] = xdp0;  gp.C[1] = xdp1;
        gemm_bs<0><<<dim3(1, BL/128, 2*KSPLIT), 256, SMEM_B>>>(gp, DIz, DIz, XD, XD, DIz/KSPLIT, KSPLIT, (size_t)BL*XD);
    }
    reduce_xd<<<(2*BL*XD + 255)/256, 256>>>();

    // ---- GEMM3 (dual): dt = softplus(x_dbl[:, :64] @ Wdt^T + bdt)  (M=2048, N=2048, K=64) ----
    {
        GemmP gp{};
        gp.Ah[0] = xdh0;  gp.Ah[1] = xdh1;  gp.Al[0] = xdl0;  gp.Al[1] = xdl1;
        gp.Bh[0] = wdtfh; gp.Bh[1] = wdtrh; gp.Bl[0] = wdtfl; gp.Bl[1] = wdtrl;
        gp.C[0] = dt0;    gp.C[1] = dt1;
        gp.bias[0] = bdt_f; gp.bias[1] = bdt_r;
        gemm_bs<1><<<dim3(DIz/128, BL/128, 2), 256, SMEM_B>>>(gp, RK, RK, DIz, DIz, RK, 1, 0);
    }

    scan_kernel<<<512, 256>>>(Dsk_f, Dsk_r);

    // ---- GEMM4: out = ycat @ wcat^T  (M=2048, N=1024, K=4096) ----
    {
        GemmP gp{};
        gp.Ah[0] = yh;  gp.Ah[1] = yh;  gp.Al[0] = yl;  gp.Al[1] = yl;
        gp.Bh[0] = wch; gp.Bh[1] = wch; gp.Bl[0] = wcl; gp.Bl[1] = wcl;
        gp.C[0] = out;  gp.C[1] = out;
        gemm_bs<0><<<dim3(Dz/128, BL/128, 1), 256, SMEM_B>>>(gp, E2, E2, Dz, Dz, E2, 1, 0);
    }
}